// round 1
// baseline (speedup 1.0000x reference)
#include <cuda_runtime.h>
#include <math.h>

#define D 128
#define MAXN 100000
#define MAXR 64

// Scratch (alloc-free rule: __device__ globals)
__device__ float g_V[MAXR * 2 * D];      // per-relation W@rel vectors, 64KB
__device__ float g_num_u[MAXN * (size_t)D];
__device__ float g_num_i[MAXN * (size_t)D];
__device__ float g_den_u[MAXN];
__device__ float g_den_i[MAXN];

// V[r][j] = sum_k W[j,k] * rel[r,k],  j in [0,256), W row-major [256,128]
__global__ void compute_V_kernel(const float* __restrict__ W,
                                 const float* __restrict__ rel) {
    __shared__ float srel[D];
    int r = blockIdx.x;
    int j = threadIdx.x;                 // 0..255
    if (j < D) srel[j] = rel[r * D + j];
    __syncthreads();
    float acc = 0.f;
#pragma unroll 8
    for (int k = 0; k < D; k++) acc = fmaf(W[j * D + k], srel[k], acc);
    g_V[r * 2 * D + j] = acc;
}

__device__ __forceinline__ void red_add_v4(float* addr, float4 v) {
    asm volatile("red.global.add.v4.f32 [%0], {%1, %2, %3, %4};"
                 :: "l"(addr), "f"(v.x), "f"(v.y), "f"(v.z), "f"(v.w)
                 : "memory");
}

// One warp per edge. Computes e_exp and accumulates numerators/denominators.
__global__ void edge_kernel(const float* __restrict__ usr,
                            const float* __restrict__ ent,
                            const int* __restrict__ head,
                            const int* __restrict__ tail,
                            const int* __restrict__ etype,
                            float* __restrict__ num_u,
                            float* __restrict__ num_i,
                            float* __restrict__ den_u,
                            float* __restrict__ den_i,
                            int E) {
    int warp = (blockIdx.x * blockDim.x + threadIdx.x) >> 5;
    int lane = threadIdx.x & 31;
    if (warp >= E) return;
    int h = head[warp];
    int t = tail[warp];
    int r = etype[warp];

    const float4* hu_p = (const float4*)(usr + (size_t)h * D);
    const float4* te_p = (const float4*)(ent + (size_t)t * D);
    const float4* vh_p = (const float4*)(g_V + r * 2 * D);
    const float4* vt_p = (const float4*)(g_V + r * 2 * D + D);

    float4 hu = hu_p[lane];
    float4 te = te_p[lane];
    float4 vh = vh_p[lane];
    float4 vt = vt_p[lane];

    float p = hu.x * vh.x + hu.y * vh.y + hu.z * vh.z + hu.w * vh.w
            + te.x * vt.x + te.y * vt.y + te.z * vt.z + te.w * vt.w;
#pragma unroll
    for (int o = 16; o; o >>= 1) p += __shfl_xor_sync(0xffffffffu, p, o);

    float e = p > 0.f ? p : 0.2f * p;    // LeakyReLU(0.2)
    float ee = expf(e);

    if (lane == 0) {
        atomicAdd(den_u + h, ee);
        atomicAdd(den_i + t, ee);
    }
    float4 nu = make_float4(te.x * ee, te.y * ee, te.z * ee, te.w * ee);
    float4 ni = make_float4(hu.x * ee, hu.y * ee, hu.z * ee, hu.w * ee);
    red_add_v4(num_u + (size_t)h * D + lane * 4, nu);
    red_add_v4(num_i + (size_t)t * D + lane * 4, ni);
}

// One warp per node: agg = num/den + x ; x += l2norm(agg)
__global__ void node_kernel(float* __restrict__ x,
                            const float* __restrict__ num,
                            const float* __restrict__ den,
                            int N) {
    int warp = (blockIdx.x * blockDim.x + threadIdx.x) >> 5;
    int lane = threadIdx.x & 31;
    if (warp >= N) return;
    float d = den[warp];
    float inv = d > 0.f ? 1.f / d : 0.f;

    float4 xv = ((const float4*)(x + (size_t)warp * D))[lane];
    float4 nv = ((const float4*)(num + (size_t)warp * D))[lane];
    float4 a;
    a.x = fmaf(nv.x, inv, xv.x);
    a.y = fmaf(nv.y, inv, xv.y);
    a.z = fmaf(nv.z, inv, xv.z);
    a.w = fmaf(nv.w, inv, xv.w);

    float ss = a.x * a.x + a.y * a.y + a.z * a.z + a.w * a.w;
#pragma unroll
    for (int o = 16; o; o >>= 1) ss += __shfl_xor_sync(0xffffffffu, ss, o);
    float nrm = sqrtf(ss);
    float s = 1.f / fmaxf(nrm, 1e-8f);

    float4 out;
    out.x = fmaf(a.x, s, xv.x);
    out.y = fmaf(a.y, s, xv.y);
    out.z = fmaf(a.z, s, xv.z);
    out.w = fmaf(a.w, s, xv.w);
    ((float4*)(x + (size_t)warp * D))[lane] = out;
}

extern "C" void kernel_launch(void* const* d_in, const int* in_sizes, int n_in,
                              void* d_out, int out_size) {
    const float* usr_in = (const float*)d_in[0];  // [Nu,128]
    const float* rel    = (const float*)d_in[1];  // [R,128]
    const float* ent_in = (const float*)d_in[2];  // [Ne,128]
    const float* W      = (const float*)d_in[3];  // [256,128]
    const int*   eidx   = (const int*)d_in[4];    // [2,E]
    const int*   etype  = (const int*)d_in[5];    // [E]

    int Nu = in_sizes[0] / D;
    int R  = in_sizes[1] / D;
    int Ne = in_sizes[2] / D;
    int E  = in_sizes[5];

    float* usr = (float*)d_out;                // output: [usr_all ; ent_all]
    float* ent = usr + (size_t)Nu * D;

    cudaMemcpyAsync(usr, usr_in, (size_t)Nu * D * sizeof(float),
                    cudaMemcpyDeviceToDevice);
    cudaMemcpyAsync(ent, ent_in, (size_t)Ne * D * sizeof(float),
                    cudaMemcpyDeviceToDevice);

    compute_V_kernel<<<R, 2 * D>>>(W, rel);

    void *p_nu, *p_ni, *p_du, *p_di;
    cudaGetSymbolAddress(&p_nu, g_num_u);
    cudaGetSymbolAddress(&p_ni, g_num_i);
    cudaGetSymbolAddress(&p_du, g_den_u);
    cudaGetSymbolAddress(&p_di, g_den_i);

    const int* head = eidx;
    const int* tail = eidx + E;

    int edge_blocks = (E + 7) / 8;             // 8 warps/block
    int nu_blocks   = (Nu + 7) / 8;
    int ni_blocks   = (Ne + 7) / 8;

    for (int hop = 0; hop < 2; hop++) {
        cudaMemsetAsync(p_nu, 0, (size_t)Nu * D * sizeof(float));
        cudaMemsetAsync(p_ni, 0, (size_t)Ne * D * sizeof(float));
        cudaMemsetAsync(p_du, 0, (size_t)Nu * sizeof(float));
        cudaMemsetAsync(p_di, 0, (size_t)Ne * sizeof(float));

        edge_kernel<<<edge_blocks, 256>>>(usr, ent, head, tail, etype,
                                          (float*)p_nu, (float*)p_ni,
                                          (float*)p_du, (float*)p_di, E);

        node_kernel<<<nu_blocks, 256>>>(usr, (const float*)p_nu,
                                        (const float*)p_du, Nu);
        node_kernel<<<ni_blocks, 256>>>(ent, (const float*)p_ni,
                                        (const float*)p_di, Ne);
    }
}

// round 2
// speedup vs baseline: 1.0621x; 1.0621x over previous
#include <cuda_runtime.h>
#include <math.h>

#define D 128
#define MAXN 100000
#define MAXR 64
#define MAXE 600000

// ---- device-global scratch (alloc-free rule) ----
__device__ float g_V[MAXR * 2 * D];                 // W @ rel, per relation: [Vh | Vt]
__device__ float g_scr_u[(size_t)MAXN * D];         // hop ping-pong buffers
__device__ float g_scr_i[(size_t)MAXN * D];
__device__ int   g_deg_u[MAXN], g_deg_i[MAXN];
__device__ int   g_off_u[MAXN + 1], g_off_i[MAXN + 1];
__device__ int   g_cur_u[MAXN], g_cur_i[MAXN];
__device__ int2  g_adj_u[MAXE];                     // (tail, rel) grouped by head
__device__ int2  g_adj_i[MAXE];                     // (head, rel) grouped by tail

// V[r][j] = sum_k W[j,k] * rel[r,k],  j in [0,256)
__global__ void compute_V_kernel(const float* __restrict__ W,
                                 const float* __restrict__ rel) {
    __shared__ float srel[D];
    int r = blockIdx.x;
    int j = threadIdx.x;
    if (j < D) srel[j] = rel[r * D + j];
    __syncthreads();
    float acc = 0.f;
#pragma unroll 8
    for (int k = 0; k < D; k++) acc = fmaf(W[j * D + k], srel[k], acc);
    g_V[r * 2 * D + j] = acc;
}

__global__ void hist_kernel(const int* __restrict__ head,
                            const int* __restrict__ tail, int E) {
    int i = blockIdx.x * blockDim.x + threadIdx.x;
    if (i < E) {
        atomicAdd(g_deg_u + head[i], 1);
        atomicAdd(g_deg_i + tail[i], 1);
    }
}

// block 0 scans deg_u -> off_u/cur_u, block 1 scans deg_i -> off_i/cur_i
__global__ void scan_kernel(int Nu, int Ne) {
    const int* deg; int* off; int* cur; int N;
    if (blockIdx.x == 0) { deg = g_deg_u; off = g_off_u; cur = g_cur_u; N = Nu; }
    else                 { deg = g_deg_i; off = g_off_i; cur = g_cur_i; N = Ne; }
    __shared__ int warp_sums[32];
    __shared__ int s_carry;
    int tid = threadIdx.x, lane = tid & 31, wid = tid >> 5;
    if (tid == 0) s_carry = 0;
    __syncthreads();
    for (int base = 0; base < N; base += 1024) {
        int i = base + tid;
        int v = (i < N) ? deg[i] : 0;
        int x = v;
#pragma unroll
        for (int o = 1; o < 32; o <<= 1) {
            int y = __shfl_up_sync(0xffffffffu, x, o);
            if (lane >= o) x += y;
        }
        if (lane == 31) warp_sums[wid] = x;
        __syncthreads();
        if (wid == 0) {
            int s = warp_sums[lane];
#pragma unroll
            for (int o = 1; o < 32; o <<= 1) {
                int y = __shfl_up_sync(0xffffffffu, s, o);
                if (lane >= o) s += y;
            }
            warp_sums[lane] = s;
        }
        __syncthreads();
        int block_prefix = (wid > 0) ? warp_sums[wid - 1] : 0;
        int incl = x + block_prefix;
        int excl = incl - v + s_carry;
        if (i < N) { off[i] = excl; cur[i] = excl; }
        __syncthreads();
        if (tid == 1023) s_carry += incl;   // incl of last thread == chunk total
        __syncthreads();
    }
    if (tid == 0) off[N] = s_carry;
}

__global__ void scatter_kernel(const int* __restrict__ head,
                               const int* __restrict__ tail,
                               const int* __restrict__ etype, int E) {
    int i = blockIdx.x * blockDim.x + threadIdx.x;
    if (i < E) {
        int h = head[i], t = tail[i], r = etype[i];
        int p = atomicAdd(g_cur_u + h, 1);
        g_adj_u[p] = make_int2(t, r);
        int q = atomicAdd(g_cur_i + t, 1);
        g_adj_i[q] = make_int2(h, r);
    }
}

// Fused: attention score + softmax + aggregation + residual + l2norm + residual.
// One warp per node. Row held in registers (float4 per lane).
__global__ __launch_bounds__(256)
void agg_kernel(const float* __restrict__ src_self,
                const float* __restrict__ src_other,
                const int* __restrict__ off,
                const int2* __restrict__ adj,
                const float* __restrict__ v_own,    // stride 256 per relation
                const float* __restrict__ v_oth,
                float* __restrict__ dst, int N) {
    int node = (blockIdx.x * blockDim.x + threadIdx.x) >> 5;
    int lane = threadIdx.x & 31;
    if (node >= N) return;
    int beg = off[node], end = off[node + 1];

    const float4 own = ((const float4*)(src_self + (size_t)node * D))[lane];
    float4 num = make_float4(0.f, 0.f, 0.f, 0.f);
    float den = 0.f;

    float4 oth, vo, vw;
    if (beg < end) {
        int2 ad = adj[beg];
        oth = ((const float4*)(src_other + (size_t)ad.x * D))[lane];
        vo  = ((const float4*)(v_own + ad.y * 2 * D))[lane];
        vw  = ((const float4*)(v_oth + ad.y * 2 * D))[lane];
    }
    for (int e = beg; e < end; e++) {
        float4 c_oth = oth, c_vo = vo, c_vw = vw;
        if (e + 1 < end) {                           // prefetch next edge
            int2 ad = adj[e + 1];
            oth = ((const float4*)(src_other + (size_t)ad.x * D))[lane];
            vo  = ((const float4*)(v_own + ad.y * 2 * D))[lane];
            vw  = ((const float4*)(v_oth + ad.y * 2 * D))[lane];
        }
        float p = own.x * c_vo.x + own.y * c_vo.y + own.z * c_vo.z + own.w * c_vo.w
                + c_oth.x * c_vw.x + c_oth.y * c_vw.y + c_oth.z * c_vw.z + c_oth.w * c_vw.w;
#pragma unroll
        for (int o = 16; o; o >>= 1) p += __shfl_xor_sync(0xffffffffu, p, o);
        float s = p > 0.f ? p : 0.2f * p;            // LeakyReLU(0.2)
        float ee = __expf(s);
        num.x = fmaf(c_oth.x, ee, num.x);
        num.y = fmaf(c_oth.y, ee, num.y);
        num.z = fmaf(c_oth.z, ee, num.z);
        num.w = fmaf(c_oth.w, ee, num.w);
        den += ee;
    }
    float inv = den > 0.f ? 1.f / den : 0.f;
    float4 a;
    a.x = fmaf(num.x, inv, own.x);
    a.y = fmaf(num.y, inv, own.y);
    a.z = fmaf(num.z, inv, own.z);
    a.w = fmaf(num.w, inv, own.w);
    float ss = a.x * a.x + a.y * a.y + a.z * a.z + a.w * a.w;
#pragma unroll
    for (int o = 16; o; o >>= 1) ss += __shfl_xor_sync(0xffffffffu, ss, o);
    float sc = 1.f / fmaxf(sqrtf(ss), 1e-8f);
    float4 out;
    out.x = fmaf(a.x, sc, own.x);
    out.y = fmaf(a.y, sc, own.y);
    out.z = fmaf(a.z, sc, own.z);
    out.w = fmaf(a.w, sc, own.w);
    ((float4*)(dst + (size_t)node * D))[lane] = out;
}

extern "C" void kernel_launch(void* const* d_in, const int* in_sizes, int n_in,
                              void* d_out, int out_size) {
    const float* usr_in = (const float*)d_in[0];  // [Nu,128]
    const float* rel    = (const float*)d_in[1];  // [R,128]
    const float* ent_in = (const float*)d_in[2];  // [Ne,128]
    const float* W      = (const float*)d_in[3];  // [256,128]
    const int*   eidx   = (const int*)d_in[4];    // [2,E]
    const int*   etype  = (const int*)d_in[5];    // [E]

    int Nu = in_sizes[0] / D;
    int R  = in_sizes[1] / D;
    int Ne = in_sizes[2] / D;
    int E  = in_sizes[5];

    float* usr_out = (float*)d_out;
    float* ent_out = usr_out + (size_t)Nu * D;

    void *p_V, *p_su, *p_si, *p_du, *p_di, *p_ou, *p_oi, *p_au, *p_ai;
    cudaGetSymbolAddress(&p_V,  g_V);
    cudaGetSymbolAddress(&p_su, g_scr_u);
    cudaGetSymbolAddress(&p_si, g_scr_i);
    cudaGetSymbolAddress(&p_du, g_deg_u);
    cudaGetSymbolAddress(&p_di, g_deg_i);
    cudaGetSymbolAddress(&p_ou, g_off_u);
    cudaGetSymbolAddress(&p_oi, g_off_i);
    cudaGetSymbolAddress(&p_au, g_adj_u);
    cudaGetSymbolAddress(&p_ai, g_adj_i);

    const float* V   = (const float*)p_V;
    const float* Vh  = V;            // first 128 of each 256-stride row
    const float* Vt  = V + D;        // second 128
    float* scr_u = (float*)p_su;
    float* scr_i = (float*)p_si;
    const int* head = eidx;
    const int* tail = eidx + E;

    // ---- CSR build ----
    cudaMemsetAsync(p_du, 0, Nu * sizeof(int));
    cudaMemsetAsync(p_di, 0, Ne * sizeof(int));
    compute_V_kernel<<<R, 2 * D>>>(W, rel);
    hist_kernel<<<(E + 255) / 256, 256>>>(head, tail, E);
    scan_kernel<<<2, 1024>>>(Nu, Ne);
    scatter_kernel<<<(E + 255) / 256, 256>>>(head, tail, etype, E);

    int gu = (Nu + 7) / 8;   // 8 warps per block
    int gi = (Ne + 7) / 8;

    // hop 1: inputs -> scratch
    agg_kernel<<<gu, 256>>>(usr_in, ent_in, (const int*)p_ou, (const int2*)p_au,
                            Vh, Vt, scr_u, Nu);
    agg_kernel<<<gi, 256>>>(ent_in, usr_in, (const int*)p_oi, (const int2*)p_ai,
                            Vt, Vh, scr_i, Ne);
    // hop 2: scratch -> d_out
    agg_kernel<<<gu, 256>>>(scr_u, scr_i, (const int*)p_ou, (const int2*)p_au,
                            Vh, Vt, usr_out, Nu);
    agg_kernel<<<gi, 256>>>(scr_i, scr_u, (const int*)p_oi, (const int2*)p_ai,
                            Vt, Vh, ent_out, Ne);
}

// round 3
// speedup vs baseline: 1.5592x; 1.4680x over previous
#include <cuda_runtime.h>
#include <math.h>

#define D 128
#define MAXN 100000
#define MAXR 64
#define MAXE 600000
#define SCAN_B 1024
#define MAXBLK 128

// ---- device-global scratch (alloc-free rule) ----
__device__ float g_V[MAXR * 2 * D];
__device__ float g_scr_u[(size_t)MAXN * D];
__device__ float g_scr_i[(size_t)MAXN * D];
__device__ int   g_deg_u[MAXN], g_deg_i[MAXN];
__device__ int   g_off_u[MAXN + 1], g_off_i[MAXN + 1];
__device__ int   g_cur_u[MAXN], g_cur_i[MAXN];
__device__ int   g_part_u[MAXBLK], g_part_i[MAXBLK];
__device__ int2  g_adj_u[MAXE];
__device__ int2  g_adj_i[MAXE];

// V[r][j] = sum_k W[j,k]*rel[r,k]; also zero degree arrays.
__global__ void compute_V_init(const float* __restrict__ W,
                               const float* __restrict__ rel,
                               int Nu, int Ne) {
    __shared__ float srel[D];
    int r = blockIdx.x, j = threadIdx.x;
    if (j < D) srel[j] = rel[r * D + j];
    __syncthreads();
    float acc = 0.f;
#pragma unroll 8
    for (int k = 0; k < D; k++) acc = fmaf(W[j * D + k], srel[k], acc);
    g_V[r * 2 * D + j] = acc;
    int idx = blockIdx.x * blockDim.x + threadIdx.x;
    int T = gridDim.x * blockDim.x;
    for (int k = idx; k < Nu; k += T) g_deg_u[k] = 0;
    for (int k = idx; k < Ne; k += T) g_deg_i[k] = 0;
}

__global__ void hist_kernel(const int* __restrict__ head,
                            const int* __restrict__ tail, int E) {
    int i = blockIdx.x * blockDim.x + threadIdx.x;
    if (i < E) {
        atomicAdd(g_deg_u + head[i], 1);
        atomicAdd(g_deg_i + tail[i], 1);
    }
}

// Per-chunk partial sums: blocks [0,nblk_u) -> u, rest -> i.
__global__ void scan_partial(int Nu, int Ne, int nblk_u) {
    int b = blockIdx.x;
    const int* deg; int* part; int N, lb;
    if (b < nblk_u) { deg = g_deg_u; part = g_part_u; N = Nu; lb = b; }
    else            { deg = g_deg_i; part = g_part_i; N = Ne; lb = b - nblk_u; }
    int tid = threadIdx.x, lane = tid & 31, wid = tid >> 5;
    int i = lb * SCAN_B + tid;
    int v = (i < N) ? deg[i] : 0;
    __shared__ int wsum[32];
#pragma unroll
    for (int o = 16; o; o >>= 1) v += __shfl_xor_sync(0xffffffffu, v, o);
    if (lane == 0) wsum[wid] = v;
    __syncthreads();
    if (wid == 0) {
        int s = wsum[lane];
#pragma unroll
        for (int o = 16; o; o >>= 1) s += __shfl_xor_sync(0xffffffffu, s, o);
        if (lane == 0) part[lb] = s;
    }
}

// Final scan: each block computes its carry from partials, scans its chunk.
__global__ void scan_final(int Nu, int Ne, int nblk_u, int nblk_i) {
    int b = blockIdx.x;
    const int* deg; const int* part; int* off; int* cur; int N, lb, nblk;
    if (b < nblk_u) { deg = g_deg_u; part = g_part_u; off = g_off_u; cur = g_cur_u;
                      N = Nu; lb = b; nblk = nblk_u; }
    else            { deg = g_deg_i; part = g_part_i; off = g_off_i; cur = g_cur_i;
                      N = Ne; lb = b - nblk_u; nblk = nblk_i; }
    int tid = threadIdx.x, lane = tid & 31, wid = tid >> 5;
    __shared__ int s_carry, s_total;
    __shared__ int wsum[32];
    if (wid == 0) {
        int c = 0, t = 0;
        for (int j = lane; j < nblk; j += 32) {
            int p = part[j];
            t += p;
            if (j < lb) c += p;
        }
#pragma unroll
        for (int o = 16; o; o >>= 1) {
            c += __shfl_xor_sync(0xffffffffu, c, o);
            t += __shfl_xor_sync(0xffffffffu, t, o);
        }
        if (lane == 0) { s_carry = c; s_total = t; }
    }
    __syncthreads();
    int i = lb * SCAN_B + tid;
    int v = (i < N) ? deg[i] : 0;
    int x = v;
#pragma unroll
    for (int o = 1; o < 32; o <<= 1) {
        int y = __shfl_up_sync(0xffffffffu, x, o);
        if (lane >= o) x += y;
    }
    if (lane == 31) wsum[wid] = x;
    __syncthreads();
    if (wid == 0) {
        int s = wsum[lane];
#pragma unroll
        for (int o = 1; o < 32; o <<= 1) {
            int y = __shfl_up_sync(0xffffffffu, s, o);
            if (lane >= o) s += y;
        }
        wsum[lane] = s;
    }
    __syncthreads();
    int incl = x + (wid ? wsum[wid - 1] : 0);
    int excl = incl - v + s_carry;
    if (i < N) { off[i] = excl; cur[i] = excl; }
    if (lb == 0 && tid == 0) off[N] = s_total;
}

__global__ void scatter_kernel(const int* __restrict__ head,
                               const int* __restrict__ tail,
                               const int* __restrict__ etype, int E) {
    int i = blockIdx.x * blockDim.x + threadIdx.x;
    if (i < E) {
        int h = head[i], t = tail[i], r = etype[i];
        g_adj_u[atomicAdd(g_cur_u + h, 1)] = make_int2(t, r);
        g_adj_i[atomicAdd(g_cur_i + t, 1)] = make_int2(h, r);
    }
}

// Fused both-sides hop kernel. One warp per node, row in registers.
// Streaming hints: self/dst evict-first so the gather table stays in L2.
__global__ __launch_bounds__(256)
void agg2_kernel(const float* __restrict__ usr, const float* __restrict__ ent,
                 float* __restrict__ usr_o, float* __restrict__ ent_o,
                 int Nu, int Ne, int gu) {
    int b = blockIdx.x;
    const float* self; const float* other; float* dst;
    const int* off; const int2* adj; int N, voff_own, voff_oth, nb;
    if (b < gu) { self = usr; other = ent; dst = usr_o; off = g_off_u;
                  adj = g_adj_u; N = Nu; voff_own = 0; voff_oth = D; nb = b; }
    else        { self = ent; other = usr; dst = ent_o; off = g_off_i;
                  adj = g_adj_i; N = Ne; voff_own = D; voff_oth = 0; nb = b - gu; }
    int wid = threadIdx.x >> 5, lane = threadIdx.x & 31;
    int node = nb * 8 + wid;
    if (node >= N) return;

    int beg = off[node];
    int n = off[node + 1] - beg;
    float4 own = __ldcs((const float4*)(self + (size_t)node * D) + lane);
    float4 num = make_float4(0.f, 0.f, 0.f, 0.f);
    float den = 0.f;

    // depth-2 pipeline over edges
    int2 ad0, ad1; float4 o0, o1;
    if (n > 0) {
        ad0 = __ldg(adj + beg);
        o0 = ((const float4*)(other + (size_t)ad0.x * D))[lane];
    }
    if (n > 1) {
        ad1 = __ldg(adj + beg + 1);
        o1 = ((const float4*)(other + (size_t)ad1.x * D))[lane];
    }
    for (int e = 0; e < n; e++) {
        int2 ad = ad0; float4 oth = o0;
        ad0 = ad1; o0 = o1;
        if (e + 2 < n) {
            ad1 = __ldg(adj + beg + e + 2);
            o1 = ((const float4*)(other + (size_t)ad1.x * D))[lane];
        }
        float4 vo = __ldg((const float4*)(g_V + ad.y * 2 * D + voff_own) + lane);
        float4 vw = __ldg((const float4*)(g_V + ad.y * 2 * D + voff_oth) + lane);
        float p = own.x * vo.x + own.y * vo.y + own.z * vo.z + own.w * vo.w
                + oth.x * vw.x + oth.y * vw.y + oth.z * vw.z + oth.w * vw.w;
#pragma unroll
        for (int o = 16; o; o >>= 1) p += __shfl_xor_sync(0xffffffffu, p, o);
        float s = p > 0.f ? p : 0.2f * p;
        float ee = __expf(s);
        num.x = fmaf(oth.x, ee, num.x);
        num.y = fmaf(oth.y, ee, num.y);
        num.z = fmaf(oth.z, ee, num.z);
        num.w = fmaf(oth.w, ee, num.w);
        den += ee;
    }
    float inv = den > 0.f ? 1.f / den : 0.f;
    float4 a;
    a.x = fmaf(num.x, inv, own.x);
    a.y = fmaf(num.y, inv, own.y);
    a.z = fmaf(num.z, inv, own.z);
    a.w = fmaf(num.w, inv, own.w);
    float ss = a.x * a.x + a.y * a.y + a.z * a.z + a.w * a.w;
#pragma unroll
    for (int o = 16; o; o >>= 1) ss += __shfl_xor_sync(0xffffffffu, ss, o);
    float sc = 1.f / fmaxf(sqrtf(ss), 1e-8f);
    float4 out;
    out.x = fmaf(a.x, sc, own.x);
    out.y = fmaf(a.y, sc, own.y);
    out.z = fmaf(a.z, sc, own.z);
    out.w = fmaf(a.w, sc, own.w);
    __stcs((float4*)(dst + (size_t)node * D) + lane, out);
}

extern "C" void kernel_launch(void* const* d_in, const int* in_sizes, int n_in,
                              void* d_out, int out_size) {
    const float* usr_in = (const float*)d_in[0];
    const float* rel    = (const float*)d_in[1];
    const float* ent_in = (const float*)d_in[2];
    const float* W      = (const float*)d_in[3];
    const int*   eidx   = (const int*)d_in[4];
    const int*   etype  = (const int*)d_in[5];

    int Nu = in_sizes[0] / D;
    int R  = in_sizes[1] / D;
    int Ne = in_sizes[2] / D;
    int E  = in_sizes[5];

    float* usr_out = (float*)d_out;
    float* ent_out = usr_out + (size_t)Nu * D;

    void *p_su, *p_si;
    cudaGetSymbolAddress(&p_su, g_scr_u);
    cudaGetSymbolAddress(&p_si, g_scr_i);
    float* scr_u = (float*)p_su;
    float* scr_i = (float*)p_si;

    const int* head = eidx;
    const int* tail = eidx + E;

    int nblk_u = (Nu + SCAN_B - 1) / SCAN_B;
    int nblk_i = (Ne + SCAN_B - 1) / SCAN_B;
    int gu = (Nu + 7) / 8, gi = (Ne + 7) / 8;

    // launches: 1..5 CSR build, 6 = agg hop1 (ncu -s 5 -c 1 lands here)
    compute_V_init<<<R, 2 * D>>>(W, rel, Nu, Ne);
    hist_kernel<<<(E + 255) / 256, 256>>>(head, tail, E);
    scan_partial<<<nblk_u + nblk_i, SCAN_B>>>(Nu, Ne, nblk_u);
    scan_final<<<nblk_u + nblk_i, SCAN_B>>>(Nu, Ne, nblk_u, nblk_i);
    scatter_kernel<<<(E + 255) / 256, 256>>>(head, tail, etype, E);

    agg2_kernel<<<gu + gi, 256>>>(usr_in, ent_in, scr_u, scr_i, Nu, Ne, gu);
    agg2_kernel<<<gu + gi, 256>>>(scr_u, scr_i, usr_out, ent_out, Nu, Ne, gu);
}